// round 9
// baseline (speedup 1.0000x reference)
#include <cuda_runtime.h>
#include <cuda_fp16.h>
#include <cstdint>

// Problem constants
#define BB_ 16
#define TT_ 8192
#define DD_ 192
#define KK_ 512
#define SPAN_ 8
#define BS_ 16384
#define NTOK_ (BB_*TT_)

// Output layout: q_out | loss | idx_out | boundaries (float32)
#define Q_ELEMS (BB_*TT_*DD_)
#define LOSS_OFF (Q_ELEMS)
#define IDX_OFF  (Q_ELEMS + 1)
#define BND_OFF  (IDX_OFF + NTOK_)

// K2: CTA = 128 segs x 512 codes; 8 chunks of 64 codes; 256 threads.
// fp16 double-split: value = v1 + v2s/2048. A resident in registers.
#define TM2_ 128
#define NC_ 64
#define NCHUNK2_ 8
#define NTHR2_ 256
#define KS16_ 12                          // k16 slabs over D=192
#define B_CHUNK_U4 (8*KS16_*32)           // 3072 uint4 = 48KB per chunk
#define K2_DYN (2*B_CHUNK_U4*16)          // 98304
#define INV2048_ (1.0f/2048.0f)

// Scratch (__device__ globals; no allocation allowed)
__device__ __align__(16) float g_pooled[BS_*DD_];       // [seg][d] for K3
__device__ uint4 g_pA4[BS_*DD_/4];                      // A fragments {a1|a2s}
__device__ uint4 g_cbF4[64*KS16_*32];                   // B fragments {b1,b2s}
__device__ float g_hnorm[KK_];
__device__ int   g_sidx[BS_];
__device__ float g_epart[BS_];
__device__ int   g_bcount;

// ---------------------------------------------------------------------------
// helpers (sm_100 base-target safe)
// ---------------------------------------------------------------------------
__device__ __forceinline__ uint32_t smem_u32(const void* p) {
    uint32_t a;
    asm("{ .reg .u64 t; cvta.to.shared.u64 t, %1; cvt.u32.u64 %0, t; }"
        : "=r"(a) : "l"(p));
    return a;
}
__device__ __forceinline__ void cp16(uint32_t dst, const void* src) {
    asm volatile("cp.async.cg.shared.global [%0], [%1], 16;"
                 :: "r"(dst), "l"(src) : "memory");
}
__device__ __forceinline__ void cp_commit() {
    asm volatile("cp.async.commit_group;" ::: "memory");
}
__device__ __forceinline__ void cp_wait1() {
    asm volatile("cp.async.wait_group 1;" ::: "memory");
}
__device__ __forceinline__ void cp_wait0() {
    asm volatile("cp.async.wait_group 0;" ::: "memory");
}
__device__ __forceinline__ uint32_t packh2(float lo, float hi) {
    __half2 h = __halves2half2(__float2half_rn(lo), __float2half_rn(hi));
    return *(uint32_t*)&h;
}
__device__ __forceinline__ float h1f(float v) {
    return __half2float(__float2half_rn(v));
}
__device__ __forceinline__ float h2sf(float v) {
    return (v - h1f(v)) * 2048.0f;
}
// D += A(16x16 f16) * B(16x8 f16), fp32 accumulate
__device__ __forceinline__ void mma16(float* c, const uint32_t* a,
                                      uint32_t b0, uint32_t b1) {
    asm volatile(
        "mma.sync.aligned.m16n8k16.row.col.f32.f16.f16.f32 "
        "{%0,%1,%2,%3}, {%4,%5,%6,%7}, {%8,%9}, {%0,%1,%2,%3};"
        : "+f"(c[0]), "+f"(c[1]), "+f"(c[2]), "+f"(c[3])
        : "r"(a[0]), "r"(a[1]), "r"(a[2]), "r"(a[3]), "r"(b0), "r"(b1));
}

// ---------------------------------------------------------------------------
// Kprep: codebook -> B-fragment order (double-fp16 split) + half norms +
// boundary-counter zero. Blocks 0..95 do fragments; blocks 0..63 also do
// a warp-per-code hnorm pass (cb rows hit L2 the second time).
// ---------------------------------------------------------------------------
__global__ void __launch_bounds__(256) k_prep(const float* __restrict__ cb)
{
    int i = blockIdx.x * 256 + threadIdx.x;     // 24576 total
    if (blockIdx.x == 0 && threadIdx.x == 0) g_bcount = 0;
    {
        int lane = i & 31;
        int ks = (i >> 5) % KS16_;
        int nt = i / (KS16_ * 32);              // 0..63
        int gid = lane >> 2, tig = lane & 3;
        const float* row = cb + (long)(nt * 8 + gid) * DD_ + ks * 16;
        float v0 = row[2 * tig], v1 = row[2 * tig + 1];
        float v2 = row[2 * tig + 8], v3 = row[2 * tig + 9];
        uint4 r;
        r.x = packh2(h1f(v0), h1f(v1));
        r.y = packh2(h1f(v2), h1f(v3));
        r.z = packh2(h2sf(v0), h2sf(v1));
        r.w = packh2(h2sf(v2), h2sf(v3));
        g_cbF4[(nt * KS16_ + ks) * 32 + lane] = r;
    }
    if (blockIdx.x < 64) {
        const int w = blockIdx.x * 8 + (threadIdx.x >> 5);
        const int lane = threadIdx.x & 31;
        float s = 0.f;
        #pragma unroll
        for (int j = 0; j < 6; j++) {
            float v = cb[(long)w * DD_ + lane + 32 * j];
            s += v * v;
        }
        #pragma unroll
        for (int m = 16; m > 0; m >>= 1) s += __shfl_xor_sync(0xffffffffu, s, m);
        if (lane == 0) g_hnorm[w] = 0.5f * s;
    }
}

// ---------------------------------------------------------------------------
// K1: boundary predictor + segment pooling.
// Emits pooled twice: plain [seg][d] (K3) and fp16-split A-fragment (K2).
// ---------------------------------------------------------------------------
__global__ void __launch_bounds__(256) k1_pool_boundary(
    const float* __restrict__ x,
    const float* __restrict__ bw,
    const float* __restrict__ bb,
    float* __restrict__ bnd_out)
{
    __shared__ float sx[256 * 33];
    __shared__ float pTc[32 * 33];     // [seg_local][d_local] pooled chunk
    __shared__ float s_bw[DD_];
    const int tid = threadIdx.x;
    const long tok0 = (long)blockIdx.x * 256;
    const int s0 = blockIdx.x * 32;

    if (tid < DD_) s_bw[tid] = bw[tid];

    float logit = 0.f;

    #pragma unroll 1
    for (int dc = 0; dc < 6; dc++) {
        for (int i = tid; i < 2048; i += 256) {
            int token = i >> 3, j4 = (i & 7) * 4;
            float4 v = *(const float4*)(x + (tok0 + token) * DD_ + dc * 32 + j4);
            float* p = &sx[token * 33 + j4];
            p[0] = v.x; p[1] = v.y; p[2] = v.z; p[3] = v.w;
        }
        __syncthreads();

        {
            const float* row = &sx[tid * 33];
            const float* bwc = &s_bw[dc * 32];
            float l = 0.f;
            #pragma unroll 8
            for (int j = 0; j < 32; j++) l += row[j] * bwc[j];
            logit += l;
        }

        // pooled: 32 segs x 32 d, 4 outputs per thread
        #pragma unroll
        for (int m = 0; m < 4; m++) {
            int o = tid + 256 * m;
            int seg = o >> 5, d = o & 31;
            float s = 0.f;
            #pragma unroll
            for (int t = 0; t < SPAN_; t++) s += sx[(seg * 8 + t) * 33 + d];
            s *= 0.125f;
            g_pooled[(long)(s0 + seg) * DD_ + dc * 32 + d] = s;
            pTc[seg * 33 + d] = s;
        }
        __syncthreads();

        // A-fragment pass: dc chunk = 2 k16 slabs x 2 m-tiles x {a1,a2s}
        {
            const int lane = tid & 31;
            const int q = tid >> 5;             // 0..7
            const int s16 = q >> 2;             // k16 slab within chunk
            const int mt = (q >> 1) & 1;        // m-tile within block
            const int which = q & 1;            // 0 = a1, 1 = a2s
            const int gid = lane >> 2, tig = lane & 3;
            const int r0 = mt * 16 + gid, r1 = r0 + 8;
            const int c0 = s16 * 16 + 2 * tig;
            float v00 = pTc[r0 * 33 + c0],     v01 = pTc[r0 * 33 + c0 + 1];
            float v02 = pTc[r0 * 33 + c0 + 8], v03 = pTc[r0 * 33 + c0 + 9];
            float v10 = pTc[r1 * 33 + c0],     v11 = pTc[r1 * 33 + c0 + 1];
            float v12 = pTc[r1 * 33 + c0 + 8], v13 = pTc[r1 * 33 + c0 + 9];
            uint4 r;
            if (which == 0) {
                r.x = packh2(h1f(v00), h1f(v01));
                r.y = packh2(h1f(v10), h1f(v11));
                r.z = packh2(h1f(v02), h1f(v03));
                r.w = packh2(h1f(v12), h1f(v13));
            } else {
                r.x = packh2(h2sf(v00), h2sf(v01));
                r.y = packh2(h2sf(v10), h2sf(v11));
                r.z = packh2(h2sf(v02), h2sf(v03));
                r.w = packh2(h2sf(v12), h2sf(v13));
            }
            int mt_g = blockIdx.x * 2 + mt;
            int b2 = mt_g >> 3;                 // k2 CTA
            int wy = mt_g & 7;                  // m-tile within k2 CTA
            int ks = dc * 2 + s16;
            g_pA4[(long)b2 * 6144 + ((wy * KS16_ + ks) * 2 + which) * 32 + lane] = r;
        }
        __syncthreads();
    }

    float lg = logit + bb[0];
    float flag = (lg > 0.f) ? 1.f : 0.f;
    bnd_out[tok0 + tid] = flag;
    unsigned m = __ballot_sync(0xffffffffu, flag > 0.f);
    if ((tid & 31) == 0) atomicAdd(&g_bcount, __popc(m));
}

// ---------------------------------------------------------------------------
// K2: double-fp16 VQ search, A resident in registers.
// 256 threads = 8 warps; warp = 1 m-tile (16 segs) x ALL 512 codes.
// A (12 ks x {a1,a2s}) loaded once via coalesced LDG -> 96 regs; smem is
// B-only (double-buffered 48KB chunks). Per chunk (64 codes) processed in
// two 4-nt halves to bound live accumulators (48 regs).
// ---------------------------------------------------------------------------
extern __shared__ __align__(1024) char k2smem[];

__global__ void __launch_bounds__(NTHR2_, 1) k2_vq()
{
    __shared__ float s_hn[KK_];

    const int tid = threadIdx.x;
    const int wy = tid >> 5, lane = tid & 31;
    const int gid = lane >> 2, tig = lane & 3;
    const int s0 = blockIdx.x * TM2_;

    uint4* smB = (uint4*)k2smem;
    const uint32_t smB_u = smem_u32(smB);

    // B chunk0 / chunk1 prefetch
    for (int i = tid; i < B_CHUNK_U4; i += NTHR2_)
        cp16(smB_u + (uint32_t)i * 16, g_cbF4 + i);
    cp_commit();
    for (int i = tid; i < B_CHUNK_U4; i += NTHR2_)
        cp16(smB_u + (uint32_t)(B_CHUNK_U4 + i) * 16, g_cbF4 + B_CHUNK_U4 + i);
    cp_commit();

    // A into registers (coalesced LDG.128)
    uint4 a1r[KS16_], a2r[KS16_];
    {
        const uint4* srcA = g_pA4 + (long)blockIdx.x * 6144
                          + wy * (KS16_ * 2 * 32) + lane;
        #pragma unroll
        for (int ks = 0; ks < KS16_; ks++) {
            a1r[ks] = srcA[ks * 64];
            a2r[ks] = srcA[ks * 64 + 32];
        }
    }
    for (int i = tid; i < KK_; i += NTHR2_) s_hn[i] = g_hnorm[i];

    float best[2]; int bidx[2];
    best[0] = best[1] = -3.0e38f; bidx[0] = bidx[1] = 0;

    for (int ch = 0; ch < NCHUNK2_; ch++) {
        if (ch < NCHUNK2_ - 1) cp_wait1(); else cp_wait0();
        __syncthreads();

        const uint4* bufB = smB + (ch & 1) * B_CHUNK_U4;

        #pragma unroll
        for (int half = 0; half < 2; half++) {
            float acc_h[4][4], acc_l1[4][4], acc_l2[4][4];
            #pragma unroll
            for (int ni = 0; ni < 4; ni++)
                #pragma unroll
                for (int j = 0; j < 4; j++) {
                    acc_h[ni][j] = 0.f; acc_l1[ni][j] = 0.f; acc_l2[ni][j] = 0.f;
                }

            const uint4* bPtr = bufB + (half * 4) * (KS16_ * 32) + lane;

            #pragma unroll 3
            for (int ks = 0; ks < KS16_; ks++) {
                const uint32_t* a1 = (const uint32_t*)&a1r[ks];
                const uint32_t* a2 = (const uint32_t*)&a2r[ks];
                #pragma unroll
                for (int ni = 0; ni < 4; ni++) {
                    uint4 b = bPtr[ni * (KS16_ * 32) + ks * 32];
                    mma16(acc_h[ni],  a1, b.x, b.y);
                    mma16(acc_l1[ni], a1, b.z, b.w);
                    mma16(acc_l2[ni], a2, b.x, b.y);
                }
            }

            // register-only epilogue for these 32 codes
            #pragma unroll
            for (int ni = 0; ni < 4; ni++) {
                const int codeb = ch * NC_ + (half * 4 + ni) * 8 + 2 * tig;
                const float hn0 = s_hn[codeb], hn1 = s_hn[codeb + 1];
                #pragma unroll
                for (int j = 0; j < 4; j++) {
                    float sc = acc_h[ni][j]
                             + (acc_l1[ni][j] + acc_l2[ni][j]) * INV2048_
                             - ((j & 1) ? hn1 : hn0);
                    int slot = j >> 1;
                    int code = codeb + (j & 1);
                    if (sc > best[slot]) { best[slot] = sc; bidx[slot] = code; }
                }
            }
        }
        __syncthreads();   // all reads of bufB done before overwrite

        if (ch < NCHUNK2_ - 2) {
            const uint4* src = g_cbF4 + (long)(ch + 2) * B_CHUNK_U4;
            uint32_t dst = smB_u + (uint32_t)((ch & 1) * B_CHUNK_U4) * 16;
            for (int i = tid; i < B_CHUNK_U4; i += NTHR2_)
                cp16(dst + (uint32_t)i * 16, src + i);
            cp_commit();
        }
    }

    // reduce over the 4 tig lanes (disjoint code classes mod 8);
    // warp owns all codes, so this is the final reduce.
    #pragma unroll
    for (int slot = 0; slot < 2; slot++) {
        float b = best[slot]; int ix = bidx[slot];
        #pragma unroll
        for (int m = 1; m <= 2; m <<= 1) {
            float ob = __shfl_xor_sync(0xffffffffu, b, m);
            int   oi = __shfl_xor_sync(0xffffffffu, ix, m);
            if (ob > b || (ob == b && oi < ix)) { b = ob; ix = oi; }
        }
        if (tig == 0) g_sidx[s0 + wy * 16 + gid + 8 * slot] = ix;
    }
}

// ---------------------------------------------------------------------------
// K3: gather + STE broadcast (float4), per-segment e_latent partial, idx_out.
// ---------------------------------------------------------------------------
__global__ void __launch_bounds__(192) k3_expand(
    const float* __restrict__ cb, float* __restrict__ out)
{
    __shared__ float se[192];
    const int tid = threadIdx.x;
    const int sl = tid / 48, slot = tid - sl * 48;
    const int s = blockIdx.x * 4 + sl;
    const int idx = g_sidx[s];
    float4 c4 = *(const float4*)(cb + (long)idx * DD_ + slot * 4);
    float4 p4 = *(const float4*)(g_pooled + (long)s * DD_ + slot * 4);
    float4 q4;
    q4.x = p4.x + (c4.x - p4.x);
    q4.y = p4.y + (c4.y - p4.y);
    q4.z = p4.z + (c4.z - p4.z);
    q4.w = p4.w + (c4.w - p4.w);
    float dx = c4.x - p4.x, dy = c4.y - p4.y, dz = c4.z - p4.z, dw = c4.w - p4.w;
    se[tid] = dx * dx + dy * dy + dz * dz + dw * dw;
    __syncthreads();
    if (slot == 0) {
        float t = 0.f;
        #pragma unroll
        for (int j = 0; j < 48; j++) t += se[sl * 48 + j];
        g_epart[s] = t;
    }
    float4* qb = (float4*)out + (long)s * 384 + slot;
    #pragma unroll
    for (int tk = 0; tk < SPAN_; tk++) qb[tk * 48] = q4;
    if (slot < SPAN_) out[IDX_OFF + s * SPAN_ + slot] = (float)idx;
}

// ---------------------------------------------------------------------------
// K4: deterministic loss reduction.
// ---------------------------------------------------------------------------
__global__ void __launch_bounds__(256) k4_loss(float* __restrict__ out)
{
    __shared__ double rd[256];
    const int tid = threadIdx.x;
    double a = 0.0;
    for (int i = tid; i < BS_; i += 256) a += (double)g_epart[i];
    rd[tid] = a;
    __syncthreads();
    for (int step = 128; step > 0; step >>= 1) {
        if (tid < step) rd[tid] += rd[tid + step];
        __syncthreads();
    }
    if (tid == 0) {
        float e_mean = (float)(rd[0] / (double)((long)BS_ * DD_));
        float bm = (float)g_bcount / (float)NTOK_;
        float dbm = bm - (1.0f / SPAN_);
        out[LOSS_OFF] = 0.25f * e_mean + 0.01f * dbm * dbm;
    }
}

// ---------------------------------------------------------------------------
extern "C" void kernel_launch(void* const* d_in, const int* in_sizes, int n_in,
                              void* d_out, int out_size)
{
    const float* x  = (const float*)d_in[0];
    const float* cb = (const float*)d_in[1];
    const float* bw = (const float*)d_in[2];
    const float* bb = (const float*)d_in[3];
    float* out = (float*)d_out;
    (void)in_sizes; (void)n_in; (void)out_size;

    cudaFuncSetAttribute(k2_vq, cudaFuncAttributeMaxDynamicSharedMemorySize,
                         K2_DYN);

    k_prep<<<96, 256>>>(cb);
    k1_pool_boundary<<<NTOK_ / 256, 256>>>(x, bw, bb, out + BND_OFF);
    k2_vq<<<BS_ / TM2_, NTHR2_, K2_DYN>>>();
    k3_expand<<<BS_ / 4, 192>>>(cb, out);
    k4_loss<<<1, 256>>>(out);
}

// round 10
// speedup vs baseline: 1.0568x; 1.0568x over previous
#include <cuda_runtime.h>
#include <cuda_fp16.h>
#include <cstdint>

// Problem constants
#define BB_ 16
#define TT_ 8192
#define DD_ 192
#define KK_ 512
#define SPAN_ 8
#define BS_ 16384
#define NTOK_ (BB_*TT_)

// Output layout: q_out | loss | idx_out | boundaries (float32)
#define Q_ELEMS (BB_*TT_*DD_)
#define LOSS_OFF (Q_ELEMS)
#define IDX_OFF  (Q_ELEMS + 1)
#define BND_OFF  (IDX_OFF + NTOK_)

// K2: CTA = 128 segs x 512 codes; 8 chunks of 64 codes; 256 threads = 8 warps
// (4 M-groups x 2 N-groups), warp = 2 m-tiles x 4 n-tiles (fat tiling:
// 0.33 LDS.128 per MMA). fp16 double-split: value = v1 + v2s/2048.
#define TM2_ 128
#define NC_ 64
#define NCHUNK2_ 8
#define NTHR2_ 256
#define KS16_ 12                          // k16 slabs over D=192
#define A_U4 6144                         // 8 mtiles x 12 ks x {a1,a2s} x 32
#define A_BYTES (A_U4*16)                 // 98304
#define B_CHUNK_U4 (8*KS16_*32)           // 3072 uint4 = 48KB per chunk
#define K2_DYN (A_BYTES + 2*B_CHUNK_U4*16)  // 196608
#define INV2048_ (1.0f/2048.0f)

// Scratch (__device__ globals; no allocation allowed)
__device__ __align__(16) float g_pooled[BS_*DD_];       // [seg][d] for K3
__device__ uint4 g_pA4[BS_*DD_/4];                      // A fragments {a1|a2s}
__device__ uint4 g_cbF4[64*KS16_*32];                   // B fragments {b1,b2s}
__device__ float g_hnorm[KK_];
__device__ int   g_sidx[BS_];
__device__ float g_epart[BS_];
__device__ int   g_bcount;

// ---------------------------------------------------------------------------
// helpers (sm_100 base-target safe)
// ---------------------------------------------------------------------------
__device__ __forceinline__ uint32_t smem_u32(const void* p) {
    uint32_t a;
    asm("{ .reg .u64 t; cvta.to.shared.u64 t, %1; cvt.u32.u64 %0, t; }"
        : "=r"(a) : "l"(p));
    return a;
}
__device__ __forceinline__ void cp16(uint32_t dst, const void* src) {
    asm volatile("cp.async.cg.shared.global [%0], [%1], 16;"
                 :: "r"(dst), "l"(src) : "memory");
}
__device__ __forceinline__ void cp_commit() {
    asm volatile("cp.async.commit_group;" ::: "memory");
}
__device__ __forceinline__ void cp_wait1() {
    asm volatile("cp.async.wait_group 1;" ::: "memory");
}
__device__ __forceinline__ void cp_wait0() {
    asm volatile("cp.async.wait_group 0;" ::: "memory");
}
__device__ __forceinline__ uint32_t packh2(float lo, float hi) {
    __half2 h = __halves2half2(__float2half_rn(lo), __float2half_rn(hi));
    return *(uint32_t*)&h;
}
__device__ __forceinline__ float h1f(float v) {
    return __half2float(__float2half_rn(v));
}
__device__ __forceinline__ float h2sf(float v) {
    return (v - h1f(v)) * 2048.0f;
}
// D += A(16x16 f16) * B(16x8 f16), fp32 accumulate
__device__ __forceinline__ void mma16(float* c, const uint32_t* a,
                                      uint32_t b0, uint32_t b1) {
    asm volatile(
        "mma.sync.aligned.m16n8k16.row.col.f32.f16.f16.f32 "
        "{%0,%1,%2,%3}, {%4,%5,%6,%7}, {%8,%9}, {%0,%1,%2,%3};"
        : "+f"(c[0]), "+f"(c[1]), "+f"(c[2]), "+f"(c[3])
        : "r"(a[0]), "r"(a[1]), "r"(a[2]), "r"(a[3]), "r"(b0), "r"(b1));
}

// ---------------------------------------------------------------------------
// Kprep: codebook -> B-fragment order (double-fp16 split) + half norms +
// boundary-counter zero.
// ---------------------------------------------------------------------------
__global__ void __launch_bounds__(256) k_prep(const float* __restrict__ cb)
{
    int i = blockIdx.x * 256 + threadIdx.x;     // 24576 total
    if (blockIdx.x == 0 && threadIdx.x == 0) g_bcount = 0;
    {
        int lane = i & 31;
        int ks = (i >> 5) % KS16_;
        int nt = i / (KS16_ * 32);              // 0..63
        int gid = lane >> 2, tig = lane & 3;
        const float* row = cb + (long)(nt * 8 + gid) * DD_ + ks * 16;
        float v0 = row[2 * tig], v1 = row[2 * tig + 1];
        float v2 = row[2 * tig + 8], v3 = row[2 * tig + 9];
        uint4 r;
        r.x = packh2(h1f(v0), h1f(v1));
        r.y = packh2(h1f(v2), h1f(v3));
        r.z = packh2(h2sf(v0), h2sf(v1));
        r.w = packh2(h2sf(v2), h2sf(v3));
        g_cbF4[(nt * KS16_ + ks) * 32 + lane] = r;
    }
    if (blockIdx.x < 64) {
        const int w = blockIdx.x * 8 + (threadIdx.x >> 5);
        const int lane = threadIdx.x & 31;
        float s = 0.f;
        #pragma unroll
        for (int j = 0; j < 6; j++) {
            float v = cb[(long)w * DD_ + lane + 32 * j];
            s += v * v;
        }
        #pragma unroll
        for (int m = 16; m > 0; m >>= 1) s += __shfl_xor_sync(0xffffffffu, s, m);
        if (lane == 0) g_hnorm[w] = 0.5f * s;
    }
}

// ---------------------------------------------------------------------------
// K1: boundary predictor + segment pooling.
// Emits pooled twice: plain [seg][d] (K3) and fp16-split A-fragment (K2).
// ---------------------------------------------------------------------------
__global__ void __launch_bounds__(256) k1_pool_boundary(
    const float* __restrict__ x,
    const float* __restrict__ bw,
    const float* __restrict__ bb,
    float* __restrict__ bnd_out)
{
    __shared__ float sx[256 * 33];
    __shared__ float pTc[32 * 33];     // [seg_local][d_local] pooled chunk
    __shared__ float s_bw[DD_];
    const int tid = threadIdx.x;
    const long tok0 = (long)blockIdx.x * 256;
    const int s0 = blockIdx.x * 32;

    if (tid < DD_) s_bw[tid] = bw[tid];

    float logit = 0.f;

    #pragma unroll 1
    for (int dc = 0; dc < 6; dc++) {
        for (int i = tid; i < 2048; i += 256) {
            int token = i >> 3, j4 = (i & 7) * 4;
            float4 v = *(const float4*)(x + (tok0 + token) * DD_ + dc * 32 + j4);
            float* p = &sx[token * 33 + j4];
            p[0] = v.x; p[1] = v.y; p[2] = v.z; p[3] = v.w;
        }
        __syncthreads();

        {
            const float* row = &sx[tid * 33];
            const float* bwc = &s_bw[dc * 32];
            float l = 0.f;
            #pragma unroll 8
            for (int j = 0; j < 32; j++) l += row[j] * bwc[j];
            logit += l;
        }

        // pooled: 32 segs x 32 d, 4 outputs per thread
        #pragma unroll
        for (int m = 0; m < 4; m++) {
            int o = tid + 256 * m;
            int seg = o >> 5, d = o & 31;
            float s = 0.f;
            #pragma unroll
            for (int t = 0; t < SPAN_; t++) s += sx[(seg * 8 + t) * 33 + d];
            s *= 0.125f;
            g_pooled[(long)(s0 + seg) * DD_ + dc * 32 + d] = s;
            pTc[seg * 33 + d] = s;
        }
        __syncthreads();

        // A-fragment pass: dc chunk = 2 k16 slabs x 2 m-tiles x {a1,a2s}
        {
            const int lane = tid & 31;
            const int q = tid >> 5;             // 0..7
            const int s16 = q >> 2;             // k16 slab within chunk
            const int mt = (q >> 1) & 1;        // m-tile within block
            const int which = q & 1;            // 0 = a1, 1 = a2s
            const int gid = lane >> 2, tig = lane & 3;
            const int r0 = mt * 16 + gid, r1 = r0 + 8;
            const int c0 = s16 * 16 + 2 * tig;
            float v00 = pTc[r0 * 33 + c0],     v01 = pTc[r0 * 33 + c0 + 1];
            float v02 = pTc[r0 * 33 + c0 + 8], v03 = pTc[r0 * 33 + c0 + 9];
            float v10 = pTc[r1 * 33 + c0],     v11 = pTc[r1 * 33 + c0 + 1];
            float v12 = pTc[r1 * 33 + c0 + 8], v13 = pTc[r1 * 33 + c0 + 9];
            uint4 r;
            if (which == 0) {
                r.x = packh2(h1f(v00), h1f(v01));
                r.y = packh2(h1f(v10), h1f(v11));
                r.z = packh2(h1f(v02), h1f(v03));
                r.w = packh2(h1f(v12), h1f(v13));
            } else {
                r.x = packh2(h2sf(v00), h2sf(v01));
                r.y = packh2(h2sf(v10), h2sf(v11));
                r.z = packh2(h2sf(v02), h2sf(v03));
                r.w = packh2(h2sf(v12), h2sf(v13));
            }
            int mt_g = blockIdx.x * 2 + mt;
            int b2 = mt_g >> 3;                 // k2 CTA
            int wy8 = mt_g & 7;                 // m-tile within k2 CTA
            int ks = dc * 2 + s16;
            g_pA4[(long)b2 * A_U4 + ((wy8 * KS16_ + ks) * 2 + which) * 32 + lane] = r;
        }
        __syncthreads();
    }

    float lg = logit + bb[0];
    float flag = (lg > 0.f) ? 1.f : 0.f;
    bnd_out[tok0 + tid] = flag;
    unsigned m = __ballot_sync(0xffffffffu, flag > 0.f);
    if ((tid & 31) == 0) atomicAdd(&g_bcount, __popc(m));
}

// ---------------------------------------------------------------------------
// K2: double-fp16 VQ search via mma.sync.m16n8k16.
// 256 threads = 8 warps (4M x 2N); warp = 2 m-tiles (32 segs) x 4 n-tiles
// (32 codes/chunk). Fat tiling: per ks, 8 LDS.128 feed 24 MMAs.
// A streamed from smem (NOT register-resident — R9 regression reverted).
// ---------------------------------------------------------------------------
extern __shared__ __align__(1024) char k2smem[];

__global__ void __launch_bounds__(NTHR2_, 1) k2_vq()
{
    __shared__ float s_hn[KK_];
    __shared__ float s_bv[2][TM2_];
    __shared__ int   s_bi[2][TM2_];

    const int tid = threadIdx.x;
    const int wid = tid >> 5, lane = tid & 31;
    const int wy = wid >> 1, wx = wid & 1;     // 4 M-groups x 2 N-groups
    const int gid = lane >> 2, tig = lane & 3;
    const int s0 = blockIdx.x * TM2_;

    uint4* smA = (uint4*)k2smem;
    uint4* smB = (uint4*)(k2smem + A_BYTES);
    const uint32_t smA_u = smem_u32(smA);
    const uint32_t smB_u = smem_u32(smB);

    // prologue: A + B chunk0 (group 0), B chunk1 (group 1)
    {
        const uint4* srcA = g_pA4 + (long)blockIdx.x * A_U4;
        for (int i = tid; i < A_U4; i += NTHR2_)
            cp16(smA_u + (uint32_t)i * 16, srcA + i);
        for (int i = tid; i < B_CHUNK_U4; i += NTHR2_)
            cp16(smB_u + (uint32_t)i * 16, g_cbF4 + i);
        cp_commit();
        for (int i = tid; i < B_CHUNK_U4; i += NTHR2_)
            cp16(smB_u + (uint32_t)(B_CHUNK_U4 + i) * 16, g_cbF4 + B_CHUNK_U4 + i);
        cp_commit();
    }
    for (int i = tid; i < KK_; i += NTHR2_) s_hn[i] = g_hnorm[i];

    float best[4]; int bidx[4];
    #pragma unroll
    for (int i = 0; i < 4; i++) { best[i] = -3.0e38f; bidx[i] = 0; }

    // acc[mt][ni][j] per family
    float acc_h[2][4][4], acc_l1[2][4][4], acc_l2[2][4][4];
    #pragma unroll
    for (int mt = 0; mt < 2; mt++)
        #pragma unroll
        for (int ni = 0; ni < 4; ni++)
            #pragma unroll
            for (int j = 0; j < 4; j++) {
                acc_h[mt][ni][j] = 0.f;
                acc_l1[mt][ni][j] = 0.f;
                acc_l2[mt][ni][j] = 0.f;
            }

    const uint4* aPtr0 = smA + (wy * 2 + 0) * (KS16_ * 2 * 32) + lane;
    const uint4* aPtr1 = smA + (wy * 2 + 1) * (KS16_ * 2 * 32) + lane;

    for (int ch = 0; ch < NCHUNK2_; ch++) {
        if (ch < NCHUNK2_ - 1) cp_wait1(); else cp_wait0();
        __syncthreads();

        const uint4* bufB = smB + (ch & 1) * B_CHUNK_U4;
        const uint4* bPtr = bufB + (wx * 4) * (KS16_ * 32) + lane;

        #pragma unroll 2
        for (int ks = 0; ks < KS16_; ks++) {
            uint4 a10 = aPtr0[ks * 64];
            uint4 a20 = aPtr0[ks * 64 + 32];
            uint4 a11 = aPtr1[ks * 64];
            uint4 a21 = aPtr1[ks * 64 + 32];
            const uint32_t* a1m0 = (const uint32_t*)&a10;
            const uint32_t* a2m0 = (const uint32_t*)&a20;
            const uint32_t* a1m1 = (const uint32_t*)&a11;
            const uint32_t* a2m1 = (const uint32_t*)&a21;
            #pragma unroll
            for (int ni = 0; ni < 4; ni++) {
                uint4 b = bPtr[ni * (KS16_ * 32) + ks * 32];
                mma16(acc_h [0][ni], a1m0, b.x, b.y);
                mma16(acc_l1[0][ni], a1m0, b.z, b.w);
                mma16(acc_l2[0][ni], a2m0, b.x, b.y);
                mma16(acc_h [1][ni], a1m1, b.x, b.y);
                mma16(acc_l1[1][ni], a1m1, b.z, b.w);
                mma16(acc_l2[1][ni], a2m1, b.x, b.y);
            }
        }
        __syncthreads();   // all reads of bufB done before overwrite

        if (ch < NCHUNK2_ - 2) {
            const uint4* src = g_cbF4 + (long)(ch + 2) * B_CHUNK_U4;
            uint32_t dst = smB_u + (uint32_t)((ch & 1) * B_CHUNK_U4) * 16;
            for (int i = tid; i < B_CHUNK_U4; i += NTHR2_)
                cp16(dst + (uint32_t)i * 16, src + i);
            cp_commit();
        }

        // scores + running argmax (codes ascending -> first-index ties)
        #pragma unroll
        for (int ni = 0; ni < 4; ni++) {
            const int codeb = ch * NC_ + (wx * 4 + ni) * 8 + 2 * tig;
            const float hn0 = s_hn[codeb], hn1 = s_hn[codeb + 1];
            #pragma unroll
            for (int mt = 0; mt < 2; mt++) {
                #pragma unroll
                for (int j = 0; j < 4; j++) {
                    float sc = acc_h[mt][ni][j]
                             + (acc_l1[mt][ni][j] + acc_l2[mt][ni][j]) * INV2048_
                             - ((j & 1) ? hn1 : hn0);
                    int slot = mt * 2 + (j >> 1);
                    int code = codeb + (j & 1);
                    if (sc > best[slot]) { best[slot] = sc; bidx[slot] = code; }
                    acc_h[mt][ni][j] = 0.f;
                    acc_l1[mt][ni][j] = 0.f;
                    acc_l2[mt][ni][j] = 0.f;
                }
            }
        }
    }

    // reduce over the 4 tig lanes (disjoint code classes mod 8)
    #pragma unroll
    for (int slot = 0; slot < 4; slot++) {
        float b = best[slot]; int ix = bidx[slot];
        #pragma unroll
        for (int m = 1; m <= 2; m <<= 1) {
            float ob = __shfl_xor_sync(0xffffffffu, b, m);
            int   oi = __shfl_xor_sync(0xffffffffu, ix, m);
            if (ob > b || (ob == b && oi < ix)) { b = ob; ix = oi; }
        }
        if (tig == 0) {
            int segl = wy * 32 + (slot >> 1) * 16 + gid + 8 * (slot & 1);
            s_bv[wx][segl] = b;
            s_bi[wx][segl] = ix;
        }
    }
    __syncthreads();

    // cross-wx combine (the two N-groups hold disjoint code halves)
    if (tid < TM2_) {
        float b0 = s_bv[0][tid], b1 = s_bv[1][tid];
        int   i0 = s_bi[0][tid], i1 = s_bi[1][tid];
        int take1 = (b1 > b0) || (b1 == b0 && i1 < i0);
        g_sidx[s0 + tid] = take1 ? i1 : i0;
    }
}

// ---------------------------------------------------------------------------
// K3: gather + STE broadcast (float4), per-segment e_latent partial, idx_out.
// ---------------------------------------------------------------------------
__global__ void __launch_bounds__(192) k3_expand(
    const float* __restrict__ cb, float* __restrict__ out)
{
    __shared__ float se[192];
    const int tid = threadIdx.x;
    const int sl = tid / 48, slot = tid - sl * 48;
    const int s = blockIdx.x * 4 + sl;
    const int idx = g_sidx[s];
    float4 c4 = *(const float4*)(cb + (long)idx * DD_ + slot * 4);
    float4 p4 = *(const float4*)(g_pooled + (long)s * DD_ + slot * 4);
    float4 q4;
    q4.x = p4.x + (c4.x - p4.x);
    q4.y = p4.y + (c4.y - p4.y);
    q4.z = p4.z + (c4.z - p4.z);
    q4.w = p4.w + (c4.w - p4.w);
    float dx = c4.x - p4.x, dy = c4.y - p4.y, dz = c4.z - p4.z, dw = c4.w - p4.w;
    se[tid] = dx * dx + dy * dy + dz * dz + dw * dw;
    __syncthreads();
    if (slot == 0) {
        float t = 0.f;
        #pragma unroll
        for (int j = 0; j < 48; j++) t += se[sl * 48 + j];
        g_epart[s] = t;
    }
    float4* qb = (float4*)out + (long)s * 384 + slot;
    #pragma unroll
    for (int tk = 0; tk < SPAN_; tk++) qb[tk * 48] = q4;
    if (slot < SPAN_) out[IDX_OFF + s * SPAN_ + slot] = (float)idx;
}

// ---------------------------------------------------------------------------
// K4: deterministic loss reduction.
// ---------------------------------------------------------------------------
__global__ void __launch_bounds__(256) k4_loss(float* __restrict__ out)
{
    __shared__ double rd[256];
    const int tid = threadIdx.x;
    double a = 0.0;
    for (int i = tid; i < BS_; i += 256) a += (double)g_epart[i];
    rd[tid] = a;
    __syncthreads();
    for (int step = 128; step > 0; step >>= 1) {
        if (tid < step) rd[tid] += rd[tid + step];
        __syncthreads();
    }
    if (tid == 0) {
        float e_mean = (float)(rd[0] / (double)((long)BS_ * DD_));
        float bm = (float)g_bcount / (float)NTOK_;
        float dbm = bm - (1.0f / SPAN_);
        out[LOSS_OFF] = 0.25f * e_mean + 0.01f * dbm * dbm;
    }
}

// ---------------------------------------------------------------------------
extern "C" void kernel_launch(void* const* d_in, const int* in_sizes, int n_in,
                              void* d_out, int out_size)
{
    const float* x  = (const float*)d_in[0];
    const float* cb = (const float*)d_in[1];
    const float* bw = (const float*)d_in[2];
    const float* bb = (const float*)d_in[3];
    float* out = (float*)d_out;
    (void)in_sizes; (void)n_in; (void)out_size;

    cudaFuncSetAttribute(k2_vq, cudaFuncAttributeMaxDynamicSharedMemorySize,
                         K2_DYN);

    k_prep<<<96, 256>>>(cb);
    k1_pool_boundary<<<NTOK_ / 256, 256>>>(x, bw, bb, out + BND_OFF);
    k2_vq<<<BS_ / TM2_, NTHR2_, K2_DYN>>>();
    k3_expand<<<BS_ / 4, 192>>>(cb, out);
    k4_loss<<<1, 256>>>(out);
}